// round 11
// baseline (speedup 1.0000x reference)
#include <cuda_runtime.h>

// embedding_pooling: out[b, (c-1)*256 + d] = relu(max_{l: label[b,l]==c} x[b,l,d]), empty->0
//  - relu + empty-case == fmax chain initialized at 0.
//  - Labels are int32 on device (proven R2 fail / R3 pass).
//
// Sequential-stream design: warp = 32 CONSECUTIVE rows (32KB linear sweep,
// 2KB bursts), CTA = 128 threads = quarter of a batch row, grid = 1024 CTAs
// (single resident wave at 8 CTAs/SM). Per-row class is warp-uniform ->
// branch into one of 5 (lo,hi) float4 accumulators. Quarters of a b are
// merged with atomicMax on int-viewed floats (valid: all candidates >= 0 and
// out is zero-filled first; for non-negative IEEE floats int order == float
// order). Zero-fill kernel guards against unspecified d_out pre-state.

#define BATCH 256
#define LSEQ  512
#define DDIM  256
#define NC    5
#define QROWS 128          // rows per CTA
#define WROWS 32           // consecutive rows per warp
#define OUT_ELEMS (BATCH * NC * DDIM)

#define FM4(a, v)  { a.x = fmaxf(a.x, v.x); a.y = fmaxf(a.y, v.y); \
                     a.z = fmaxf(a.z, v.z); a.w = fmaxf(a.w, v.w); }

#define ACC(c, vl, vh) { if (c == 1)      { FM4(a1l, vl) FM4(a1h, vh) } \
                         else if (c == 2) { FM4(a2l, vl) FM4(a2h, vh) } \
                         else if (c == 3) { FM4(a3l, vl) FM4(a3h, vh) } \
                         else if (c == 4) { FM4(a4l, vl) FM4(a4h, vh) } \
                         else if (c == 5) { FM4(a5l, vl) FM4(a5h, vh) } }

__global__ void zero_out_kernel(int4* __restrict__ out)
{
    // 327680 ints = 81920 int4; 320 blocks x 256 threads, 1 store each.
    out[blockIdx.x * 256 + threadIdx.x] = make_int4(0, 0, 0, 0);
}

__global__ __launch_bounds__(128, 8)
void embedding_pooling_kernel(const float* __restrict__ x,
                              const int* __restrict__ labels,
                              int* __restrict__ out)     // int view for atomicMax
{
    __shared__ int    s_cls[QROWS];
    __shared__ float4 s_red[4][NC][64];   // 20 KB

    const int tid  = threadIdx.x;
    const int w    = tid >> 5;
    const int lane = tid & 31;
    const int b    = blockIdx.x >> 2;
    const int quarter = blockIdx.x & 3;
    const int row0 = b * LSEQ + quarter * QROWS;   // first global row of this CTA

    if (tid < QROWS) s_cls[tid] = labels[row0 + tid];
    __syncthreads();

    // ---- Linear sweep: warp w owns local rows [w*32, w*32+32), consecutive.
    const float4* __restrict__ X4 = (const float4*)x + (size_t)row0 * (DDIM / 4);

    float4 a1l = make_float4(0.f, 0.f, 0.f, 0.f);
    float4 a1h = a1l, a2l = a1l, a2h = a1l, a3l = a1l, a3h = a1l;
    float4 a4l = a1l, a4h = a1l, a5l = a1l, a5h = a1l;

    const int kbeg = w * WROWS;
#pragma unroll 4
    for (int k = kbeg; k < kbeg + WROWS; k += 2) {
        const int c0 = s_cls[k];
        const int c1 = s_cls[k + 1];
        float4 v0l, v0h, v1l, v1h;
        if (c0) {
            v0l = X4[(size_t)k * 64 + lane];
            v0h = X4[(size_t)k * 64 + 32 + lane];
        }
        if (c1) {
            v1l = X4[(size_t)(k + 1) * 64 + lane];
            v1h = X4[(size_t)(k + 1) * 64 + 32 + lane];
        }
        ACC(c0, v0l, v0h);
        ACC(c1, v1l, v1h);
    }

    // ---- Park per-warp results.
    s_red[w][0][lane] = a1l;  s_red[w][0][32 + lane] = a1h;
    s_red[w][1][lane] = a2l;  s_red[w][1][32 + lane] = a2h;
    s_red[w][2][lane] = a3l;  s_red[w][2][32 + lane] = a3h;
    s_red[w][3][lane] = a4l;  s_red[w][3][32 + lane] = a4h;
    s_red[w][4][lane] = a5l;  s_red[w][4][32 + lane] = a5h;
    __syncthreads();

    // ---- Fold 4 warps, then merge quarters via int atomicMax (values >= 0,
    //      out zero-filled; for non-negative floats int order == float order).
    for (int i = tid; i < NC * 64; i += 128) {
        const int cls = i >> 6;
        const int col = i & 63;
        float4 m = s_red[0][cls][col];
#pragma unroll
        for (int g = 1; g < 4; g++) {
            const float4 v = s_red[g][cls][col];
            FM4(m, v);
        }
        int* o = out + (size_t)b * (NC * DDIM) + cls * DDIM + col * 4;
        atomicMax(o + 0, __float_as_int(m.x));
        atomicMax(o + 1, __float_as_int(m.y));
        atomicMax(o + 2, __float_as_int(m.z));
        atomicMax(o + 3, __float_as_int(m.w));
    }
}

extern "C" void kernel_launch(void* const* d_in, const int* in_sizes, int n_in,
                              void* d_out, int out_size)
{
    const float* x      = (const float*)d_in[0];
    const int*   labels = (const int*)d_in[1];
    int*         out    = (int*)d_out;

    zero_out_kernel<<<OUT_ELEMS / 4 / 256, 256>>>((int4*)out);
    embedding_pooling_kernel<<<BATCH * (LSEQ / QROWS), 128>>>(x, labels, out);
}

// round 12
// speedup vs baseline: 1.2865x; 1.2865x over previous
#include <cuda_runtime.h>

// embedding_pooling: out[b, (c-1)*256 + d] = relu(max_{l: label[b,l]==c} x[b,l,d]), empty->0
//  - relu + empty-case == fmax chain initialized at 0.
//  - Labels are int32 on device (proven R2 fail / R3 pass).
//
// R7 skeleton (1280 CTAs x 128 thr, ballot-gather, single resident wave) with
// the streaming loop restructured for MLP=8: each thread owns ONE float4
// column (64-thread team covers a whole 1KB row), 8 rows batched per
// macro-iteration -> 8 independent LDG.128 in flight per thread at ~50 regs
// (9 CTAs/SM keeps all 1280 CTAs in one wave).

#define BATCH 256
#define LSEQ  512
#define DDIM  256
#define NC    5
#define NW    4

#define FM4(a, v)  { a.x = fmaxf(a.x, v.x); a.y = fmaxf(a.y, v.y); \
                     a.z = fmaxf(a.z, v.z); a.w = fmaxf(a.w, v.w); }

__global__ __launch_bounds__(128, 9)
void embedding_pooling_kernel(const float* __restrict__ x,
                              const int* __restrict__ labels,
                              float* __restrict__ out)
{
    __shared__ int    s_idx[LSEQ];
    __shared__ int    s_base[17];
    __shared__ float4 s_red[2][64];

    const int tid  = threadIdx.x;
    const int w    = tid >> 5;
    const int lane = tid & 31;
    const int b    = blockIdx.x / NC;
    const int c    = (blockIdx.x % NC) + 1;

    // ---- Phase 1: ballot-ordered compaction of l with label == c.
    // 512 labels = 16 chunks of 32 in ascending order: chunk = k*NW + w.
    const int* lab_row = labels + (size_t)b * LSEQ;
    bool     f[4];
    unsigned m[4];
#pragma unroll
    for (int k = 0; k < 4; k++) {
        f[k] = (lab_row[tid + 128 * k] == c);
        m[k] = __ballot_sync(0xffffffffu, f[k]);
    }
    if (lane == 0) {
#pragma unroll
        for (int k = 0; k < 4; k++)
            s_base[k * NW + w] = __popc(m[k]);
    }
    __syncthreads();
    if (tid == 0) {
        int acc = 0;
#pragma unroll
        for (int i = 0; i < 16; i++) {
            const int t = s_base[i];
            s_base[i] = acc;
            acc += t;
        }
        s_base[16] = acc;
    }
    __syncthreads();
    const unsigned below = (1u << lane) - 1u;
#pragma unroll
    for (int k = 0; k < 4; k++)
        if (f[k]) s_idx[s_base[k * NW + w] + __popc(m[k] & below)] = tid + 128 * k;
    __syncthreads();
    const int n = s_base[16];

    // ---- Phase 2: team-strided max. Team (64 thr) owns rows j == team (mod 2);
    // thread owns float4 column col. 8 rows per macro-iter -> 8 LDG.128 in flight.
    const int team = tid >> 6;            // 0..1
    const int col  = tid & 63;            // float4 column 0..63
    const float4* __restrict__ Xb = (const float4*)x + (size_t)b * LSEQ * (DDIM / 4);

    float4 acc = make_float4(0.f, 0.f, 0.f, 0.f);
    int j = team;
    for (; j + 14 < n; j += 16) {
        const int l0 = s_idx[j];
        const int l1 = s_idx[j +  2];
        const int l2 = s_idx[j +  4];
        const int l3 = s_idx[j +  6];
        const int l4 = s_idx[j +  8];
        const int l5 = s_idx[j + 10];
        const int l6 = s_idx[j + 12];
        const int l7 = s_idx[j + 14];
        const float4 v0 = Xb[(size_t)l0 * 64 + col];
        const float4 v1 = Xb[(size_t)l1 * 64 + col];
        const float4 v2 = Xb[(size_t)l2 * 64 + col];
        const float4 v3 = Xb[(size_t)l3 * 64 + col];
        const float4 v4 = Xb[(size_t)l4 * 64 + col];
        const float4 v5 = Xb[(size_t)l5 * 64 + col];
        const float4 v6 = Xb[(size_t)l6 * 64 + col];
        const float4 v7 = Xb[(size_t)l7 * 64 + col];
        FM4(acc, v0); FM4(acc, v1); FM4(acc, v2); FM4(acc, v3);
        FM4(acc, v4); FM4(acc, v5); FM4(acc, v6); FM4(acc, v7);
    }
    for (; j < n; j += 2) {
        const float4 v = Xb[(size_t)s_idx[j] * 64 + col];
        FM4(acc, v);
    }

    s_red[team][col] = acc;
    __syncthreads();

    // ---- Phase 3: fold the 2 teams; one float4 store per column.
    if (tid < 64) {
        float4 mm = s_red[0][tid];
        const float4 v = s_red[1][tid];
        FM4(mm, v);
        float4* O4 = (float4*)out;
        O4[(size_t)b * (NC * (DDIM / 4)) + (size_t)(c - 1) * (DDIM / 4) + tid] = mm;
    }
}

extern "C" void kernel_launch(void* const* d_in, const int* in_sizes, int n_in,
                              void* d_out, int out_size)
{
    const float* x      = (const float*)d_in[0];
    const int*   labels = (const int*)d_in[1];
    float*       out    = (float*)d_out;

    embedding_pooling_kernel<<<BATCH * NC, 128>>>(x, labels, out);
}